// round 4
// baseline (speedup 1.0000x reference)
#include <cuda_runtime.h>
#include <math.h>

// ---------------- configuration ----------------
#define THREADS 512
#define RPT 4               // rows per thread (low reg pressure -> 2 CTAs/SM)
#define RB (THREADS * RPT)  // rows per block = 2048
#define CTILE 512           // columns per block tile (== THREADS)
#define MAXP 16384
#define MAXCH (MAXP / CTILE)

// ---------------- device scratch ----------------
__device__ float g_part[2][MAXCH][MAXP];
__device__ float g_bsum[2][64];

// ---------------- packed f32x2 helpers ----------------
typedef unsigned long long ull;

__device__ __forceinline__ ull pack2(float x, float y) {
    ull r;
    asm("mov.b64 %0, {%1, %2};" : "=l"(r) : "f"(x), "f"(y));
    return r;
}
__device__ __forceinline__ void unpack2(ull v, float& x, float& y) {
    asm("mov.b64 {%0, %1}, %2;" : "=f"(x), "=f"(y) : "l"(v));
}
__device__ __forceinline__ ull fma2(ull a, ull b, ull c) {
    ull d;
    asm("fma.rn.f32x2 %0, %1, %2, %3;" : "=l"(d) : "l"(a), "l"(b), "l"(c));
    return d;
}

// ---------------- kernel 1: pairwise max-score ----------------
// score = a.b - 0.5*|b|^2 ; maximizing score == minimizing distance.
__global__ void __launch_bounds__(THREADS, 2)
k_pairs(const float* __restrict__ tp, const float* __restrict__ pp,
        int N, int M) {
    const int dir = blockIdx.z;
    const float* __restrict__ A = dir ? pp : tp;
    const float* __restrict__ B = dir ? tp : pp;
    const int NA = dir ? M : N;
    const int NB = dir ? N : M;

    // Interleaved packed layout per column pair j (cols 2j, 2j+1):
    //   sB[j*8+0..1]=(bx0,bx1)  sB[j*8+2..3]=(by0,by1)
    //   sB[j*8+4..5]=(bz0,bz1)  sB[j*8+6..7]=(nh0,nh1)
    __shared__ __align__(16) float sB[CTILE * 4];

    const int tid = threadIdx.x;
    const int rbase = blockIdx.x * RB;
    if (rbase >= NA) return;

    // ---- stage column tile (one column per thread) ----
    {
        int col = blockIdx.y * CTILE + tid;
        float bx = 0.f, by = 0.f, bz = 0.f, nh = -1e30f;  // pad never wins
        if (col < NB) {
            bx = B[3 * col + 0];
            by = B[3 * col + 1];
            bz = B[3 * col + 2];
            nh = -0.5f * (bx * bx + by * by + bz * bz);
        }
        int j = tid >> 1, l = tid & 1;
        sB[j * 8 + 0 + l] = bx;
        sB[j * 8 + 2 + l] = by;
        sB[j * 8 + 4 + l] = bz;
        sB[j * 8 + 6 + l] = nh;
    }
    __syncthreads();

    // ---- this thread's rows, duplicated into both packed lanes ----
    ull axx[RPT], ayy[RPT], azz[RPT];
    #pragma unroll
    for (int r = 0; r < RPT; r++) {
        int row = rbase + r * THREADS + tid;
        int rr = (row < NA) ? row : 0;
        float ax = A[3 * rr + 0];
        float ay = A[3 * rr + 1];
        float az = A[3 * rr + 2];
        axx[r] = pack2(ax, ax);
        ayy[r] = pack2(ay, ay);
        azz[r] = pack2(az, az);
    }

    float m0[RPT], m1[RPT];
    #pragma unroll
    for (int r = 0; r < RPT; r++) { m0[r] = -1e30f; m1[r] = -1e30f; }

    const ulonglong2* __restrict__ pB = reinterpret_cast<const ulonglong2*>(sB);

    // ---- main loop: 2 columns x 4 rows per iteration ----
    #pragma unroll 4
    for (int j = 0; j < CTILE / 2; j++) {
        ulonglong2 v0 = pB[2 * j];      // LDS.128: bxx, byy (broadcast)
        ulonglong2 v1 = pB[2 * j + 1];  // LDS.128: bzz, nh2
        #pragma unroll
        for (int r = 0; r < RPT; r++) {
            ull t = fma2(axx[r], v0.x, v1.y);
            t = fma2(ayy[r], v0.y, t);
            t = fma2(azz[r], v1.x, t);
            float lo, hi;
            unpack2(t, lo, hi);     // register aliasing, no real MOV
            m0[r] = fmaxf(m0[r], lo);
            m1[r] = fmaxf(m1[r], hi);
        }
    }

    // ---- write per-(block,chunk) partial max; coalesced, race-free ----
    #pragma unroll
    for (int r = 0; r < RPT; r++) {
        int row = rbase + r * THREADS + tid;
        if (row < NA)
            g_part[dir][blockIdx.y][row] = fmaxf(m0[r], m1[r]);
    }
}

// ---------------- kernel 2: reduce chunks, distances, block sums ----------------
#define FTHREADS 256
__global__ void k_final(const float* __restrict__ tp, const float* __restrict__ pp,
                        int N, int M, int nch, float* __restrict__ out) {
    const int dir = blockIdx.y;
    const float* __restrict__ A = dir ? pp : tp;
    const int NA = dir ? M : N;
    const int i = blockIdx.x * FTHREADS + threadIdx.x;

    float dist = 0.f;
    if (i < NA) {
        float s = -1e30f;
        for (int c = 0; c < nch; c++)
            s = fmaxf(s, g_part[dir][c][i]);
        float ax = A[3 * i + 0];
        float ay = A[3 * i + 1];
        float az = A[3 * i + 2];
        float sa = ax * ax + ay * ay + az * az;
        dist = sqrtf(fmaxf(sa - 2.0f * s, 0.0f));
        if (dir == 1) out[1 + i] = dist;  // mins_seeds
    }

    __shared__ float red[FTHREADS];
    red[threadIdx.x] = dist;
    __syncthreads();
    for (int s = FTHREADS / 2; s > 0; s >>= 1) {
        if (threadIdx.x < s) red[threadIdx.x] += red[threadIdx.x + s];
        __syncthreads();
    }
    if (threadIdx.x == 0) g_bsum[dir][blockIdx.x] = red[0];
}

// ---------------- kernel 3: final sums + scalars ----------------
__global__ void k_out(int N, int M, int nb, float* __restrict__ out) {
    __shared__ float s[128];
    int t = threadIdx.x;  // blockDim = 64
    s[t]      = (t < nb) ? g_bsum[0][t] : 0.f;
    s[64 + t] = (t < nb) ? g_bsum[1][t] : 0.f;
    __syncthreads();
    #pragma unroll
    for (int st = 32; st > 0; st >>= 1) {
        if (t < st) {
            s[t] += s[t + st];
            s[64 + t] += s[64 + t + st];
        }
        __syncthreads();
    }
    if (t == 0) {
        float loss = s[0] / (float)N;
        float loss_seeds = s[64] / (float)M;
        out[0] = loss + loss_seeds;
        out[1 + M] = loss;
        out[2 + M] = loss_seeds;
    }
}

// ---------------- launch ----------------
extern "C" void kernel_launch(void* const* d_in, const int* in_sizes, int n_in,
                              void* d_out, int out_size) {
    const float* tp = (const float*)d_in[0];
    const float* pp = (const float*)d_in[1];
    float* out = (float*)d_out;
    const int N = in_sizes[0] / 3;
    const int M = in_sizes[1] / 3;
    const int maxP = (N > M) ? N : M;

    const int nch = (maxP + CTILE - 1) / CTILE;
    dim3 g1((maxP + RB - 1) / RB, nch, 2);   // (6, 24, 2) = 288 blocks, 2/SM
    k_pairs<<<g1, THREADS>>>(tp, pp, N, M);

    const int nb = (maxP + FTHREADS - 1) / FTHREADS;
    dim3 g2(nb, 2);
    k_final<<<g2, FTHREADS>>>(tp, pp, N, M, nch, out);

    k_out<<<1, 64>>>(N, M, nb, out);
}

// round 5
// speedup vs baseline: 1.0970x; 1.0970x over previous
#include <cuda_runtime.h>
#include <math.h>

// ---------------- configuration ----------------
#define THREADS 256
#define RPT 8               // rows per thread
#define RB (THREADS * RPT)  // rows per block = 2048
#define CTILE 256           // columns per block tile (== THREADS)
#define MAXP 16384
#define MAXCH 64            // col chunks (12288/256 = 48)
#define MAXSL 64            // row slices = blocks_x * warps (6*8 = 48)

// ---------------- device scratch (race-free, fully overwritten) ----------------
__device__ float g_rpart[MAXCH][MAXP];  // [col-chunk][row] : min over chunk of (|b|^2 - 2 a.b)
__device__ float g_cpart[MAXSL][MAXP];  // [row-slice][col] : min over slice of d^2
__device__ float g_bsum[2][64];

// ---------------- packed f32x2 helpers ----------------
typedef unsigned long long ull;

__device__ __forceinline__ ull pack2(float x, float y) {
    ull r;
    asm("mov.b64 %0, {%1, %2};" : "=l"(r) : "f"(x), "f"(y));
    return r;
}
__device__ __forceinline__ void unpack2(ull v, float& x, float& y) {
    asm("mov.b64 {%0, %1}, %2;" : "=f"(x), "=f"(y) : "l"(v));
}
__device__ __forceinline__ ull fma2(ull a, ull b, ull c) {
    ull d;
    asm("fma.rn.f32x2 %0, %1, %2, %3;" : "=l"(d) : "l"(a), "l"(b), "l"(c));
    return d;
}
__device__ __forceinline__ ull add2(ull a, ull b) {
    ull d;
    asm("add.rn.f32x2 %0, %1, %2;" : "=l"(d) : "l"(a), "l"(b));
    return d;
}

// ---------------- kernel 1: single-pass score tile, dual min ----------------
// rows = true_pos, cols = pred_pos.
//   t  = |b|^2 - 2 a.b          (row-min surrogate; d^2 = |a|^2 + t)
//   tc = t + |a|^2  = d^2       (col-min, exact)
__global__ void __launch_bounds__(THREADS, 2)
k_pairs(const float* __restrict__ tp, const float* __restrict__ pp,
        int N, int M) {
    // Interleaved packed layout per col pair j (cols 2j, 2j+1):
    //   sB[j*8+0..1]=(bx0,bx1) sB[j*8+2..3]=(by0,by1)
    //   sB[j*8+4..5]=(bz0,bz1) sB[j*8+6..7]=(sb0,sb1)  sb=|b|^2
    __shared__ __align__(16) float sB[CTILE * 4];

    const int tid = threadIdx.x;
    const int lane = tid & 31;
    const int wid = tid >> 5;
    const int rbase = blockIdx.x * RB;
    if (rbase >= N) return;   // never triggers for exact grids

    // ---- stage column tile (one column per thread) ----
    {
        int col = blockIdx.y * CTILE + tid;
        float bx = 0.f, by = 0.f, bz = 0.f, sb = 3e37f;  // pad never wins a min
        if (col < M) {
            bx = pp[3 * col + 0];
            by = pp[3 * col + 1];
            bz = pp[3 * col + 2];
            sb = bx * bx + by * by + bz * bz;
        }
        int j = tid >> 1, l = tid & 1;
        sB[j * 8 + 0 + l] = bx;
        sB[j * 8 + 2 + l] = by;
        sB[j * 8 + 4 + l] = bz;
        sB[j * 8 + 6 + l] = sb;
    }
    __syncthreads();

    // ---- this thread's rows: store (-2a) packed-dup, plus |a|^2 packed-dup ----
    ull axx[RPT], ayy[RPT], azz[RPT], saa[RPT];
    #pragma unroll
    for (int r = 0; r < RPT; r++) {
        int row = rbase + r * THREADS + tid;
        int rr = (row < N) ? row : 0;      // dup row 0: harmless for min
        float ax = tp[3 * rr + 0];
        float ay = tp[3 * rr + 1];
        float az = tp[3 * rr + 2];
        float sa = ax * ax + ay * ay + az * az;
        ax *= -2.f; ay *= -2.f; az *= -2.f;
        axx[r] = pack2(ax, ax);
        ayy[r] = pack2(ay, ay);
        azz[r] = pack2(az, az);
        saa[r] = pack2(sa, sa);
    }

    float m0[RPT], m1[RPT];
    #pragma unroll
    for (int r = 0; r < RPT; r++) { m0[r] = 3e38f; m1[r] = 3e38f; }

    const ulonglong2* __restrict__ pB = reinterpret_cast<const ulonglong2*>(sB);
    const int slice = blockIdx.x * (THREADS / 32) + wid;
    const int cbase = blockIdx.y * CTILE;

    // ---- main loop over column pairs ----
    #pragma unroll 2
    for (int j = 0; j < CTILE / 2; j++) {
        ulonglong2 v0 = pB[2 * j];      // bxx, byy (broadcast)
        ulonglong2 v1 = pB[2 * j + 1];  // bzz, sb2
        float cm0 = 3e38f, cm1 = 3e38f;
        #pragma unroll
        for (int r = 0; r < RPT; r++) {
            ull t = fma2(axx[r], v0.x, v1.y);
            t = fma2(ayy[r], v0.y, t);
            t = fma2(azz[r], v1.x, t);      // t = sb - 2 a.b
            float lo, hi;
            unpack2(t, lo, hi);
            m0[r] = fminf(m0[r], lo);       // row-min (per column lane)
            m1[r] = fminf(m1[r], hi);
            ull tc = add2(t, saa[r]);        // tc = d^2
            float clo, chi;
            unpack2(tc, clo, chi);
            cm0 = fminf(cm0, clo);           // col-min over this thread's rows
            cm1 = fminf(cm1, chi);
        }
        // warp-reduce col minima over 32 lanes (256 rows per warp)
        #pragma unroll
        for (int o = 16; o > 0; o >>= 1) {
            cm0 = fminf(cm0, __shfl_xor_sync(0xFFFFFFFFu, cm0, o));
            cm1 = fminf(cm1, __shfl_xor_sync(0xFFFFFFFFu, cm1, o));
        }
        if (lane == 0) {
            int c = cbase + 2 * j;
            g_cpart[slice][c] = cm0;
            g_cpart[slice][c + 1] = cm1;
        }
    }

    // ---- write row-min partials (coalesced, race-free: chunk = blockIdx.y) ----
    #pragma unroll
    for (int r = 0; r < RPT; r++) {
        int row = rbase + r * THREADS + tid;
        if (row < N)
            g_rpart[blockIdx.y][row] = fminf(m0[r], m1[r]);
    }
}

// ---------------- kernel 2: reduce partials, distances, block sums ----------------
#define FTHREADS 256
__global__ void k_final(const float* __restrict__ tp,
                        int N, int M, int nch, int nsl, float* __restrict__ out) {
    const int dir = blockIdx.y;
    const int i = blockIdx.x * FTHREADS + threadIdx.x;

    float dist = 0.f;
    if (dir == 0) {
        if (i < N) {
            float v = 3e38f;
            for (int c = 0; c < nch; c++)
                v = fminf(v, g_rpart[c][i]);
            float ax = tp[3 * i + 0];
            float ay = tp[3 * i + 1];
            float az = tp[3 * i + 2];
            float d2 = (ax * ax + ay * ay + az * az) + v;
            dist = sqrtf(fmaxf(d2, 0.0f));
        }
    } else {
        if (i < M) {
            float v = 3e38f;
            for (int s = 0; s < nsl; s++)
                v = fminf(v, g_cpart[s][i]);
            dist = sqrtf(fmaxf(v, 0.0f));
            out[1 + i] = dist;  // mins_seeds
        }
    }

    __shared__ float red[FTHREADS];
    red[threadIdx.x] = dist;
    __syncthreads();
    for (int s = FTHREADS / 2; s > 0; s >>= 1) {
        if (threadIdx.x < s) red[threadIdx.x] += red[threadIdx.x + s];
        __syncthreads();
    }
    if (threadIdx.x == 0) g_bsum[dir][blockIdx.x] = red[0];
}

// ---------------- kernel 3: final sums + scalars ----------------
__global__ void k_out(int N, int M, int nb, float* __restrict__ out) {
    __shared__ float s[128];
    int t = threadIdx.x;  // blockDim = 64
    s[t]      = (t < nb) ? g_bsum[0][t] : 0.f;
    s[64 + t] = (t < nb) ? g_bsum[1][t] : 0.f;
    __syncthreads();
    #pragma unroll
    for (int st = 32; st > 0; st >>= 1) {
        if (t < st) {
            s[t] += s[t + st];
            s[64 + t] += s[64 + t + st];
        }
        __syncthreads();
    }
    if (t == 0) {
        float loss = s[0] / (float)N;
        float loss_seeds = s[64] / (float)M;
        out[0] = loss + loss_seeds;
        out[1 + M] = loss;
        out[2 + M] = loss_seeds;
    }
}

// ---------------- launch ----------------
extern "C" void kernel_launch(void* const* d_in, const int* in_sizes, int n_in,
                              void* d_out, int out_size) {
    const float* tp = (const float*)d_in[0];
    const float* pp = (const float*)d_in[1];
    float* out = (float*)d_out;
    const int N = in_sizes[0] / 3;
    const int M = in_sizes[1] / 3;
    const int maxP = (N > M) ? N : M;

    const int bx = (N + RB - 1) / RB;        // row blocks (6)
    const int nch = (M + CTILE - 1) / CTILE; // col chunks (48)
    const int nsl = bx * (THREADS / 32);     // row slices (48)

    dim3 g1(bx, nch);                         // (6,48) = 288 blocks, 2/SM
    k_pairs<<<g1, THREADS>>>(tp, pp, N, M);

    const int nb = (maxP + FTHREADS - 1) / FTHREADS;  // 48
    dim3 g2(nb, 2);
    k_final<<<g2, FTHREADS>>>(tp, N, M, nch, nsl, out);

    k_out<<<1, 64>>>(N, M, nb, out);
}